// round 7
// baseline (speedup 1.0000x reference)
#include <cuda_runtime.h>
#include <stdint.h>

#define G_MEAN_F 85.384f
#define G_STD_F  53.798f

// Compile-time 289-bit validity mask for offset (DR,DC): bit p=r*17+c set iff
// (r,c) is a valid 'a' position: r <= 16-DR and (DC>=0 ? c <= 16-DC : c >= -DC)
template<int DR, int DC>
struct OffMask {
    uint32_t m[10];
    constexpr OffMask() : m{} {
        const int adc = DC < 0 ? -DC : DC;
        for (int r = 0; r <= 16 - DR; ++r)
            for (int c = 0; c < 17; ++c) {
                bool ok = (DC >= 0) ? (c <= 16 - DC) : (c >= adc);
                if (ok) { int p = r * 17 + c; m[p >> 5] |= (1u << (p & 31)); }
            }
    }
};

// GLCM features for one offset from 4 cumulative bit-planes (289-bit bitmaps).
// C[l] = bitmap of (q >= l+1). feat: {contrast, homogeneity, energy, corr, entropy}
template<int DR, int DC>
__device__ __forceinline__ void do_offset(const uint32_t C[4][11], float feat[5])
{
    constexpr int K   = DR * 17 + DC;
    constexpr int WO  = K >> 5;
    constexpr int SH  = K & 31;
    constexpr int ADC = DC < 0 ? -DC : DC;
    constexpr int NW  = ((17 - DR) * 17 + 31) >> 5;
    constexpr int TOT = (17 - DR) * (17 - ADC);
    constexpr OffMask<DR, DC> MK{};

    int Mi[4] = {0,0,0,0}, Mj[4] = {0,0,0,0};
    int M[16];
    #pragma unroll
    for (int i = 0; i < 16; ++i) M[i] = 0;

    #pragma unroll
    for (int w = 0; w < NW; ++w) {
        const uint32_t mk = MK.m[w];
        uint32_t s0 = __funnelshift_r(C[0][w+WO], C[0][w+WO+1], SH) & mk;
        uint32_t s1 = __funnelshift_r(C[1][w+WO], C[1][w+WO+1], SH) & mk;
        uint32_t s2 = __funnelshift_r(C[2][w+WO], C[2][w+WO+1], SH) & mk;
        uint32_t s3 = __funnelshift_r(C[3][w+WO], C[3][w+WO+1], SH) & mk;
        Mj[0] += __popc(s0); Mj[1] += __popc(s1);
        Mj[2] += __popc(s2); Mj[3] += __popc(s3);
        #pragma unroll
        for (int i = 0; i < 4; ++i) {
            uint32_t a = C[i][w];
            Mi[i]    += __popc(a & mk);
            M[i*4+0] += __popc(a & s0);
            M[i*4+1] += __popc(a & s1);
            M[i*4+2] += __popc(a & s2);
            M[i*4+3] += __popc(a & s3);
        }
    }

    // Cumulative table Mc[i][j] = N(a>=i, b>=j) -> cell counts via inclusion-exclusion
    int Mc[25];
    Mc[0] = TOT;
    Mc[1] = Mj[0]; Mc[2] = Mj[1]; Mc[3] = Mj[2]; Mc[4] = Mj[3];
    #pragma unroll
    for (int i = 1; i < 5; ++i) {
        Mc[i*5] = Mi[i-1];
        #pragma unroll
        for (int j = 1; j < 5; ++j) Mc[i*5+j] = M[(i-1)*4 + (j-1)];
    }
    int c[25];
    #pragma unroll
    for (int i = 0; i < 5; ++i)
        #pragma unroll
        for (int j = 0; j < 5; ++j) {
            int v = Mc[i*5+j];
            if (i < 4) v -= Mc[(i+1)*5+j];
            if (j < 4) v -= Mc[i*5+j+1];
            if (i < 4 && j < 4) v += Mc[(i+1)*5+j+1];
            c[i*5+j] = v;
        }

    const float invTot = 1.0f / (2.0f * (float)TOT);

    // symmetrized counts S = C + C^T (upper triangle incl. diag)
    int s00 = c[0]*2,  s11 = c[6]*2,  s22 = c[12]*2, s33 = c[18]*2, s44 = c[24]*2;
    int s01 = c[1]+c[5],   s02 = c[2]+c[10],  s03 = c[3]+c[15],  s04 = c[4]+c[20];
    int s12 = c[7]+c[11],  s13 = c[8]+c[16],  s14 = c[9]+c[21];
    int s23 = c[13]+c[17], s24 = c[14]+c[22];
    int s34 = c[19]+c[23];

    // contrast
    int ci = (s01 + s12 + s23 + s34) + 4*(s02 + s13 + s24) + 9*(s03 + s14) + 16*s04;
    feat[0] = 2.0f * invTot * (float)ci;

    // homogeneity
    float hoU = 0.5f*(float)(s01+s12+s23+s34)
              + 0.2f*(float)(s02+s13+s24)
              + 0.1f*(float)(s03+s14)
              + (1.0f/17.0f)*(float)s04;
    feat[1] = invTot * ((float)(s00+s11+s22+s33+s44) + 2.0f*hoU);

    // energy
    int e2i = s00*s00 + s11*s11 + s22*s22 + s33*s33 + s44*s44
            + 2*(s01*s01 + s02*s02 + s03*s03 + s04*s04
               + s12*s12 + s13*s13 + s14*s14
               + s23*s23 + s24*s24 + s34*s34);
    feat[2] = invTot * sqrtf((float)e2i);

    // correlation (symmetric => Pi == Pj)
    int t1 = s01+s11+s12+s13+s14;
    int t2 = s02+s12+s22+s23+s24;
    int t3 = s03+s13+s23+s33+s34;
    int t4 = s04+s14+s24+s34+s44;
    float mu  = invTot * (float)(t1 + 2*t2 + 3*t3 + 4*t4);
    float e2m = invTot * (float)(t1 + 4*t2 + 9*t3 + 16*t4);
    float varm = e2m - mu * mu;
    int wij = s11 + 4*s22 + 9*s33 + 16*s44
            + 2*(2*s12 + 3*s13 + 4*s14 + 6*s23 + 8*s24 + 12*s34);
    float cov = invTot * (float)wij - mu * mu;
    feat[3] = (varm < 1e-15f) ? 1.0f : __fdividef(cov, fmaxf(varm, 1e-30f));

    // entropy: off-diagonal cells counted twice
    float ent = 0.0f;
    {
        float g;
        g = (float)s00*invTot; ent += g*__log2f(g+1e-8f);
        g = (float)s11*invTot; ent += g*__log2f(g+1e-8f);
        g = (float)s22*invTot; ent += g*__log2f(g+1e-8f);
        g = (float)s33*invTot; ent += g*__log2f(g+1e-8f);
        g = (float)s44*invTot; ent += g*__log2f(g+1e-8f);
        g = (float)s01*invTot; ent += 2.0f*g*__log2f(g+1e-8f);
        g = (float)s02*invTot; ent += 2.0f*g*__log2f(g+1e-8f);
        g = (float)s03*invTot; ent += 2.0f*g*__log2f(g+1e-8f);
        g = (float)s04*invTot; ent += 2.0f*g*__log2f(g+1e-8f);
        g = (float)s12*invTot; ent += 2.0f*g*__log2f(g+1e-8f);
        g = (float)s13*invTot; ent += 2.0f*g*__log2f(g+1e-8f);
        g = (float)s14*invTot; ent += 2.0f*g*__log2f(g+1e-8f);
        g = (float)s23*invTot; ent += 2.0f*g*__log2f(g+1e-8f);
        g = (float)s24*invTot; ent += 2.0f*g*__log2f(g+1e-8f);
        g = (float)s34*invTot; ent += 2.0f*g*__log2f(g+1e-8f);
    }
    feat[4] = -ent;
}

// 128 threads, min 6 blocks/SM => 24 warps/SM, 3872 warps / 3552 slots = 1.09 waves
__global__ void __launch_bounds__(128, 6) glcm_feat_kernel(const float* __restrict__ x,
                                                           float* __restrict__ out)
{
    // 58 unique per-block feature sums: [0..3] stats, [4..7] hist, [8+u*5+k] glcm
    __shared__ float sacc[58];

    const int tid = threadIdx.x;
    const int b   = blockIdx.y;
    int wi = blockIdx.x * 128 + tid;
    const bool valid = (wi < 15376);
    if (wi >= 15376) wi = 15375;
    const int ix = wi / 124;
    const int iy = wi - ix * 124;

    for (int i = tid; i < 58; i += 128) sacc[i] = 0.0f;
    __syncthreads();

    const float* base = x + ((size_t)b << 18) + (size_t)(ix * 4) * 512 + (size_t)(iy * 4);

    const float B1 = 0.5f;
    const float B2 = (float)(85.384 - 53.798);
    const float B3 = 85.384f;
    const float B4 = (float)(85.384 + 53.798);

    // cumulative bit-planes of the whole 17x17 window: C[l] = bitmap(q >= l+1)
    uint32_t C[4][11];
    #pragma unroll
    for (int j = 0; j < 4; ++j)
        #pragma unroll
        for (int w = 0; w < 11; ++w) C[j][w] = 0u;

    float sum = 0.f, sq = 0.f, mxv = 0.f, mnv = 1e30f;

    // ---- load, stats, quantize, build register bitmaps ----
    #pragma unroll
    for (int r = 0; r < 17; ++r) {
        const float* row = base + r * 512;
        const float4* p4 = (const float4*)row;   // iy*4 floats => 16B aligned
        float4 q0 = p4[0], q1 = p4[1], q2 = p4[2], q3 = p4[3];
        float px[17] = {q0.x,q0.y,q0.z,q0.w, q1.x,q1.y,q1.z,q1.w,
                        q2.x,q2.y,q2.z,q2.w, q3.x,q3.y,q3.z,q3.w, row[16]};
        uint32_t g1=0,g2=0,g3=0,g4=0;
        #pragma unroll
        for (int v = 0; v < 17; ++v) {
            float pv = px[v];
            sum += pv;
            float d = pv - G_MEAN_F;
            sq = fmaf(d, d, sq);
            mxv = fmaxf(mxv, pv);
            mnv = fminf(mnv, pv);
            uint32_t bit = 1u << v;
            if (pv >= B1) g1 |= bit;
            if (pv >= B2) g2 |= bit;
            if (pv >= B3) g3 |= bit;
            if (pv >= B4) g4 |= bit;
        }
        const int bp = r * 17;
        const int w0 = bp >> 5;
        const int sh = bp & 31;
        C[0][w0] |= g1 << sh;
        C[1][w0] |= g2 << sh;
        C[2][w0] |= g3 << sh;
        C[3][w0] |= g4 << sh;
        if (sh > 15) {   // row spills into next word (compile-time condition)
            C[0][w0+1] |= g1 >> (32 - sh);
            C[1][w0+1] |= g2 >> (32 - sh);
            C[2][w0+1] |= g3 >> (32 - sh);
            C[3][w0+1] |= g4 >> (32 - sh);
        }
    }

    // ---- stats + histogram channels (0..7): fire-and-forget shared atomics ----
    {
        int P1=0,P2=0,P3=0,P4=0;
        #pragma unroll
        for (int w = 0; w < 10; ++w) {
            P1 += __popc(C[0][w]); P2 += __popc(C[1][w]);
            P3 += __popc(C[2][w]); P4 += __popc(C[3][w]);
        }
        int h1 = P1 - P2, h2 = P2 - P3, h3 = P3 - P4, h4 = P4;

        const float inv289 = 1.0f / 289.0f;
        float mean  = sum * inv289;
        float var0  = fmaxf(sq * inv289 - (mean - G_MEAN_F) * (mean - G_MEAN_F), 0.0f);
        float stdv  = sqrtf(var0);
        float mnorm = mean * (1.0f / G_MEAN_F);

        if (valid) {
            atomicAdd(&sacc[0], mnorm);
            atomicAdd(&sacc[1], stdv * (1.0f / G_STD_F));
            atomicAdd(&sacc[2], (mxv - mnorm) * (1.0f / G_STD_F));
            atomicAdd(&sacc[3], (mnorm - mnv) * (1.0f / G_STD_F));

            int toti = h1 + h2 + h3 + h4;
            float invt = (toti > 0) ? __fdividef(1.0f, (float)toti) : 0.0f;
            atomicAdd(&sacc[4], (float)h1 * invt);
            atomicAdd(&sacc[5], (float)h2 * invt);
            atomicAdd(&sacc[6], (float)h3 * invt);
            atomicAdd(&sacc[7], (float)h4 * invt);
        }
    }

    // ---- GLCM: 10 unique offsets, accumulate unique features ----
    float feat[5];
    #define EMIT(U) do { if (valid) { \
        atomicAdd(&sacc[8 + (U)*5 + 0], feat[0]); \
        atomicAdd(&sacc[8 + (U)*5 + 1], feat[1]); \
        atomicAdd(&sacc[8 + (U)*5 + 2], feat[2]); \
        atomicAdd(&sacc[8 + (U)*5 + 3], feat[3]); \
        atomicAdd(&sacc[8 + (U)*5 + 4], feat[4]); } } while (0)

    do_offset<0, 1>(C, feat); EMIT(0);
    do_offset<1, 1>(C, feat); EMIT(1);
    do_offset<1, 0>(C, feat); EMIT(2);
    do_offset<1,-1>(C, feat); EMIT(3);
    do_offset<0, 2>(C, feat); EMIT(4);
    do_offset<2, 0>(C, feat); EMIT(5);
    do_offset<0, 4>(C, feat); EMIT(6);
    do_offset<3, 3>(C, feat); EMIT(7);
    do_offset<4, 0>(C, feat); EMIT(8);
    do_offset<3,-3>(C, feat); EMIT(9);
    #undef EMIT

    __syncthreads();
    // expand 58 unique sums -> 68 output channels
    // output ch = 8 + 12*k + slot ; slot -> unique offset:
    if (tid < 68) {
        float v;
        if (tid < 8) {
            v = sacc[tid];
        } else {
            const int U[12] = {0,1,2,3,4,1,5,3,6,7,8,9};
            int k    = (tid - 8) / 12;
            int slot = (tid - 8) % 12;
            v = sacc[8 + U[slot] * 5 + k];
        }
        atomicAdd(&out[b * 68 + tid], v * (1.0f / 15376.0f));
    }
}

extern "C" void kernel_launch(void* const* d_in, const int* in_sizes, int n_in,
                              void* d_out, int out_size) {
    const float* x = (const float*)d_in[0];
    float* out = (float*)d_out;
    cudaMemsetAsync(out, 0, (size_t)out_size * sizeof(float), 0);
    dim3 grid(121, 8);   // 121*128 = 15488 >= 15376 windows per image, y = batch
    glcm_feat_kernel<<<grid, 128>>>(x, out);
}

// round 8
// speedup vs baseline: 2.5635x; 2.5635x over previous
#include <cuda_runtime.h>
#include <stdint.h>

#define G_MEAN_F 85.384f
#define G_STD_F  53.798f

static __device__ __forceinline__ float warp_sum(float f) {
    #pragma unroll
    for (int o = 16; o; o >>= 1) f += __shfl_down_sync(0xffffffffu, f, o);
    return f;
}

// Compile-time 289-bit validity mask for offset (DR,DC): bit p=r*17+c set iff
// (r,c) is a valid 'a' position: r <= 16-DR and (DC>=0 ? c <= 16-DC : c >= -DC)
template<int DR, int DC>
struct OffMask {
    uint32_t m[10];
    constexpr OffMask() : m{} {
        const int adc = DC < 0 ? -DC : DC;
        for (int r = 0; r <= 16 - DR; ++r)
            for (int c = 0; c < 17; ++c) {
                bool ok = (DC >= 0) ? (c <= 16 - DC) : (c >= adc);
                if (ok) { int p = r * 17 + c; m[p >> 5] |= (1u << (p & 31)); }
            }
    }
};

// GLCM features for one offset from 4 cumulative bit-planes (289-bit bitmaps).
// C[l] = bitmap of (q >= l+1). feat: {contrast, homogeneity, energy, corr, entropy}
template<int DR, int DC>
__device__ __forceinline__ void do_offset(const uint32_t C[4][11], float feat[5])
{
    constexpr int K   = DR * 17 + DC;
    constexpr int WO  = K >> 5;
    constexpr int SH  = K & 31;
    constexpr int ADC = DC < 0 ? -DC : DC;
    constexpr int NW  = ((17 - DR) * 17 + 31) >> 5;
    constexpr int TOT = (17 - DR) * (17 - ADC);
    constexpr OffMask<DR, DC> MK{};

    int Mi[4] = {0,0,0,0}, Mj[4] = {0,0,0,0};
    int M[16];
    #pragma unroll
    for (int i = 0; i < 16; ++i) M[i] = 0;

    #pragma unroll
    for (int w = 0; w < NW; ++w) {
        const uint32_t mk = MK.m[w];
        uint32_t s0 = __funnelshift_r(C[0][w+WO], C[0][w+WO+1], SH) & mk;
        uint32_t s1 = __funnelshift_r(C[1][w+WO], C[1][w+WO+1], SH) & mk;
        uint32_t s2 = __funnelshift_r(C[2][w+WO], C[2][w+WO+1], SH) & mk;
        uint32_t s3 = __funnelshift_r(C[3][w+WO], C[3][w+WO+1], SH) & mk;
        Mj[0] += __popc(s0); Mj[1] += __popc(s1);
        Mj[2] += __popc(s2); Mj[3] += __popc(s3);
        #pragma unroll
        for (int i = 0; i < 4; ++i) {
            uint32_t a = C[i][w];
            Mi[i]    += __popc(a & mk);
            M[i*4+0] += __popc(a & s0);
            M[i*4+1] += __popc(a & s1);
            M[i*4+2] += __popc(a & s2);
            M[i*4+3] += __popc(a & s3);
        }
    }

    // Cumulative table Mc[i][j] = N(a>=i, b>=j) -> cell counts via inclusion-exclusion
    int Mc[25];
    Mc[0] = TOT;
    Mc[1] = Mj[0]; Mc[2] = Mj[1]; Mc[3] = Mj[2]; Mc[4] = Mj[3];
    #pragma unroll
    for (int i = 1; i < 5; ++i) {
        Mc[i*5] = Mi[i-1];
        #pragma unroll
        for (int j = 1; j < 5; ++j) Mc[i*5+j] = M[(i-1)*4 + (j-1)];
    }
    int c[25];
    #pragma unroll
    for (int i = 0; i < 5; ++i)
        #pragma unroll
        for (int j = 0; j < 5; ++j) {
            int v = Mc[i*5+j];
            if (i < 4) v -= Mc[(i+1)*5+j];
            if (j < 4) v -= Mc[i*5+j+1];
            if (i < 4 && j < 4) v += Mc[(i+1)*5+j+1];
            c[i*5+j] = v;
        }

    const float invTot = 1.0f / (2.0f * (float)TOT);

    // symmetrized counts S = C + C^T (upper triangle incl. diag)
    int s00 = c[0]*2,  s11 = c[6]*2,  s22 = c[12]*2, s33 = c[18]*2, s44 = c[24]*2;
    int s01 = c[1]+c[5],   s02 = c[2]+c[10],  s03 = c[3]+c[15],  s04 = c[4]+c[20];
    int s12 = c[7]+c[11],  s13 = c[8]+c[16],  s14 = c[9]+c[21];
    int s23 = c[13]+c[17], s24 = c[14]+c[22];
    int s34 = c[19]+c[23];

    // contrast
    int ci = (s01 + s12 + s23 + s34) + 4*(s02 + s13 + s24) + 9*(s03 + s14) + 16*s04;
    feat[0] = 2.0f * invTot * (float)ci;

    // homogeneity
    float hoU = 0.5f*(float)(s01+s12+s23+s34)
              + 0.2f*(float)(s02+s13+s24)
              + 0.1f*(float)(s03+s14)
              + (1.0f/17.0f)*(float)s04;
    feat[1] = invTot * ((float)(s00+s11+s22+s33+s44) + 2.0f*hoU);

    // energy
    int e2i = s00*s00 + s11*s11 + s22*s22 + s33*s33 + s44*s44
            + 2*(s01*s01 + s02*s02 + s03*s03 + s04*s04
               + s12*s12 + s13*s13 + s14*s14
               + s23*s23 + s24*s24 + s34*s34);
    feat[2] = invTot * sqrtf((float)e2i);

    // correlation (symmetric => Pi == Pj)
    int t1 = s01+s11+s12+s13+s14;
    int t2 = s02+s12+s22+s23+s24;
    int t3 = s03+s13+s23+s33+s34;
    int t4 = s04+s14+s24+s34+s44;
    float mu  = invTot * (float)(t1 + 2*t2 + 3*t3 + 4*t4);
    float e2m = invTot * (float)(t1 + 4*t2 + 9*t3 + 16*t4);
    float varm = e2m - mu * mu;
    int wij = s11 + 4*s22 + 9*s33 + 16*s44
            + 2*(2*s12 + 3*s13 + 4*s14 + 6*s23 + 8*s24 + 12*s34);
    float cov = invTot * (float)wij - mu * mu;
    feat[3] = (varm < 1e-15f) ? 1.0f : __fdividef(cov, fmaxf(varm, 1e-30f));

    // entropy: off-diagonal cells counted twice
    float ent = 0.0f;
    {
        float g;
        g = (float)s00*invTot; ent += g*__log2f(g+1e-8f);
        g = (float)s11*invTot; ent += g*__log2f(g+1e-8f);
        g = (float)s22*invTot; ent += g*__log2f(g+1e-8f);
        g = (float)s33*invTot; ent += g*__log2f(g+1e-8f);
        g = (float)s44*invTot; ent += g*__log2f(g+1e-8f);
        g = (float)s01*invTot; ent += 2.0f*g*__log2f(g+1e-8f);
        g = (float)s02*invTot; ent += 2.0f*g*__log2f(g+1e-8f);
        g = (float)s03*invTot; ent += 2.0f*g*__log2f(g+1e-8f);
        g = (float)s04*invTot; ent += 2.0f*g*__log2f(g+1e-8f);
        g = (float)s12*invTot; ent += 2.0f*g*__log2f(g+1e-8f);
        g = (float)s13*invTot; ent += 2.0f*g*__log2f(g+1e-8f);
        g = (float)s14*invTot; ent += 2.0f*g*__log2f(g+1e-8f);
        g = (float)s23*invTot; ent += 2.0f*g*__log2f(g+1e-8f);
        g = (float)s24*invTot; ent += 2.0f*g*__log2f(g+1e-8f);
        g = (float)s34*invTot; ent += 2.0f*g*__log2f(g+1e-8f);
    }
    feat[4] = -ent;
}

static __device__ __forceinline__ void emit_feats(const float feat[5], int s1, int s2,
                                                  float valid, float* sacc, bool lane0)
{
    #pragma unroll
    for (int k = 0; k < 5; ++k) {
        float f = warp_sum(feat[k] * valid);
        if (lane0) {
            int base = 8 + 12 * k;
            atomicAdd(&sacc[base + s1], f);
            if (s2 >= 0) atomicAdd(&sacc[base + s2], f);
        }
    }
}

// One window's full pipeline: load/stats/quantize + 10 GLCM offsets, block-accumulate
static __device__ __forceinline__ void process_window(const float* __restrict__ base,
                                                      float valid, float* sacc, bool lane0)
{
    const float B1 = 0.5f;
    const float B2 = (float)(85.384 - 53.798);
    const float B3 = 85.384f;
    const float B4 = (float)(85.384 + 53.798);

    // cumulative bit-planes of the whole 17x17 window: C[l] = bitmap(q >= l+1)
    uint32_t C[4][11];
    #pragma unroll
    for (int j = 0; j < 4; ++j)
        #pragma unroll
        for (int w = 0; w < 11; ++w) C[j][w] = 0u;

    float sum = 0.f, sq = 0.f, mxv = 0.f, mnv = 1e30f;

    #pragma unroll
    for (int r = 0; r < 17; ++r) {
        const float* row = base + r * 512;
        const float4* p4 = (const float4*)row;   // window col start is 16B aligned
        float4 q0 = p4[0], q1 = p4[1], q2 = p4[2], q3 = p4[3];
        float px[17] = {q0.x,q0.y,q0.z,q0.w, q1.x,q1.y,q1.z,q1.w,
                        q2.x,q2.y,q2.z,q2.w, q3.x,q3.y,q3.z,q3.w, row[16]};
        uint32_t g1=0,g2=0,g3=0,g4=0;
        #pragma unroll
        for (int v = 0; v < 17; ++v) {
            float pv = px[v];
            sum += pv;
            float d = pv - G_MEAN_F;
            sq = fmaf(d, d, sq);
            mxv = fmaxf(mxv, pv);
            mnv = fminf(mnv, pv);
            uint32_t bit = 1u << v;
            if (pv >= B1) g1 |= bit;
            if (pv >= B2) g2 |= bit;
            if (pv >= B3) g3 |= bit;
            if (pv >= B4) g4 |= bit;
        }
        const int bp = r * 17;
        const int w0 = bp >> 5;
        const int sh = bp & 31;
        C[0][w0] |= g1 << sh;
        C[1][w0] |= g2 << sh;
        C[2][w0] |= g3 << sh;
        C[3][w0] |= g4 << sh;
        if (sh > 15) {   // row spills into next word (compile-time condition)
            C[0][w0+1] |= g1 >> (32 - sh);
            C[1][w0+1] |= g2 >> (32 - sh);
            C[2][w0+1] |= g3 >> (32 - sh);
            C[3][w0+1] |= g4 >> (32 - sh);
        }
    }

    // ---- stats + histogram channels (0..7) ----
    {
        int P1=0,P2=0,P3=0,P4=0;
        #pragma unroll
        for (int w = 0; w < 10; ++w) {
            P1 += __popc(C[0][w]); P2 += __popc(C[1][w]);
            P3 += __popc(C[2][w]); P4 += __popc(C[3][w]);
        }
        int h1 = P1 - P2, h2 = P2 - P3, h3 = P3 - P4, h4 = P4;

        const float inv289 = 1.0f / 289.0f;
        float mean  = sum * inv289;
        float var0  = fmaxf(sq * inv289 - (mean - G_MEAN_F) * (mean - G_MEAN_F), 0.0f);
        float stdv  = sqrtf(var0);
        float mnorm = mean * (1.0f / G_MEAN_F);

        float f;
        f = warp_sum(mnorm * valid);                            if (lane0) atomicAdd(&sacc[0], f);
        f = warp_sum((stdv * (1.0f/G_STD_F)) * valid);          if (lane0) atomicAdd(&sacc[1], f);
        f = warp_sum(((mxv - mnorm) * (1.0f/G_STD_F)) * valid); if (lane0) atomicAdd(&sacc[2], f);
        f = warp_sum(((mnorm - mnv) * (1.0f/G_STD_F)) * valid); if (lane0) atomicAdd(&sacc[3], f);

        int toti = h1 + h2 + h3 + h4;
        float invt = (toti > 0) ? __fdividef(1.0f, (float)toti) : 0.0f;
        f = warp_sum((float)h1 * invt * valid);                 if (lane0) atomicAdd(&sacc[4], f);
        f = warp_sum((float)h2 * invt * valid);                 if (lane0) atomicAdd(&sacc[5], f);
        f = warp_sum((float)h3 * invt * valid);                 if (lane0) atomicAdd(&sacc[6], f);
        f = warp_sum((float)h4 * invt * valid);                 if (lane0) atomicAdd(&sacc[7], f);
    }

    // ---- GLCM: 10 unique offsets (slots: (1,1)->1&5, (1,-1)->3&7) ----
    float feat[5];
    do_offset<0, 1>(C, feat); emit_feats(feat,  0, -1, valid, sacc, lane0);
    do_offset<1, 1>(C, feat); emit_feats(feat,  1,  5, valid, sacc, lane0);
    do_offset<1, 0>(C, feat); emit_feats(feat,  2, -1, valid, sacc, lane0);
    do_offset<1,-1>(C, feat); emit_feats(feat,  3,  7, valid, sacc, lane0);
    do_offset<0, 2>(C, feat); emit_feats(feat,  4, -1, valid, sacc, lane0);
    do_offset<2, 0>(C, feat); emit_feats(feat,  6, -1, valid, sacc, lane0);
    do_offset<0, 4>(C, feat); emit_feats(feat,  8, -1, valid, sacc, lane0);
    do_offset<3, 3>(C, feat); emit_feats(feat,  9, -1, valid, sacc, lane0);
    do_offset<4, 0>(C, feat); emit_feats(feat, 10, -1, valid, sacc, lane0);
    do_offset<3,-3>(C, feat); emit_feats(feat, 11, -1, valid, sacc, lane0);
}

// 128 threads, min 5 blocks/SM (reg budget 102). 2 windows/thread:
// grid = 61*8 = 488 blocks <= 740 resident slots => SINGLE wave, no tail.
__global__ void __launch_bounds__(128, 5) glcm_feat_kernel(const float* __restrict__ x,
                                                           float* __restrict__ out)
{
    __shared__ float sacc[68];

    const int tid = threadIdx.x;
    const int b   = blockIdx.y;
    const bool lane0 = ((tid & 31) == 0);

    for (int i = tid; i < 68; i += 128) sacc[i] = 0.0f;
    __syncthreads();

    const float* img = x + ((size_t)b << 18);

    #pragma unroll 1
    for (int ws = 0; ws < 2; ++ws) {
        int wi = (blockIdx.x * 2 + ws) * 128 + tid;
        const float valid = (wi < 15376) ? 1.0f : 0.0f;
        if (wi >= 15376) wi = 15375;
        const int ix = wi / 124;
        const int iy = wi - ix * 124;
        const float* base = img + (size_t)(ix * 4) * 512 + (size_t)(iy * 4);
        process_window(base, valid, sacc, lane0);
    }

    __syncthreads();
    if (tid < 68) atomicAdd(&out[b * 68 + tid], sacc[tid] * (1.0f / 15376.0f));
}

extern "C" void kernel_launch(void* const* d_in, const int* in_sizes, int n_in,
                              void* d_out, int out_size) {
    const float* x = (const float*)d_in[0];
    float* out = (float*)d_out;
    cudaMemsetAsync(out, 0, (size_t)out_size * sizeof(float), 0);
    dim3 grid(61, 8);   // 61 blocks * 256 windows = 15616 >= 15376, single wave
    glcm_feat_kernel<<<grid, 128>>>(x, out);
}

// round 9
// speedup vs baseline: 2.6728x; 1.0427x over previous
#include <cuda_runtime.h>
#include <stdint.h>

#define G_MEAN_F 85.384f
#define G_STD_F  53.798f

static __device__ __forceinline__ float warp_sum(float f) {
    #pragma unroll
    for (int o = 16; o; o >>= 1) f += __shfl_down_sync(0xffffffffu, f, o);
    return f;
}

// Compile-time 289-bit validity mask for offset (DR,DC): bit p=r*17+c set iff
// (r,c) is a valid 'a' position: r <= 16-DR and (DC>=0 ? c <= 16-DC : c >= -DC)
template<int DR, int DC>
struct OffMask {
    uint32_t m[10];
    constexpr OffMask() : m{} {
        const int adc = DC < 0 ? -DC : DC;
        for (int r = 0; r <= 16 - DR; ++r)
            for (int c = 0; c < 17; ++c) {
                bool ok = (DC >= 0) ? (c <= 16 - DC) : (c >= adc);
                if (ok) { int p = r * 17 + c; m[p >> 5] |= (1u << (p & 31)); }
            }
    }
};

// GLCM features for one offset from 4 cumulative bit-planes (289-bit bitmaps).
// C[l] = bitmap of (q >= l+1). feat: {contrast, homogeneity, energy, corr, entropy}
// Pairwise counts accumulated PACKED 2x16-bit per register (max count 320 < 65536,
// low half < 2^16 so no carry into high half).
template<int DR, int DC>
__device__ __forceinline__ void do_offset(const uint32_t C[4][11], float feat[5])
{
    constexpr int K   = DR * 17 + DC;
    constexpr int WO  = K >> 5;
    constexpr int SH  = K & 31;
    constexpr int ADC = DC < 0 ? -DC : DC;
    constexpr int NW  = ((17 - DR) * 17 + 31) >> 5;
    constexpr int TOT = (17 - DR) * (17 - ADC);
    constexpr OffMask<DR, DC> MK{};

    // packed accumulators: Mp[i*2+0] = M[i][0] | M[i][1]<<16 ; Mp[i*2+1] = M[i][2] | M[i][3]<<16
    uint32_t Mp[8];
    #pragma unroll
    for (int i = 0; i < 8; ++i) Mp[i] = 0u;
    uint32_t MiP0 = 0u, MiP1 = 0u;   // Mi[0]|Mi[1]<<16, Mi[2]|Mi[3]<<16
    uint32_t MjP0 = 0u, MjP1 = 0u;   // Mj[0]|Mj[1]<<16, Mj[2]|Mj[3]<<16

    #pragma unroll
    for (int w = 0; w < NW; ++w) {
        const uint32_t mk = MK.m[w];
        uint32_t s0 = __funnelshift_r(C[0][w+WO], C[0][w+WO+1], SH) & mk;
        uint32_t s1 = __funnelshift_r(C[1][w+WO], C[1][w+WO+1], SH) & mk;
        uint32_t s2 = __funnelshift_r(C[2][w+WO], C[2][w+WO+1], SH) & mk;
        uint32_t s3 = __funnelshift_r(C[3][w+WO], C[3][w+WO+1], SH) & mk;
        MjP0 += (uint32_t)__popc(s0) + ((uint32_t)__popc(s1) << 16);
        MjP1 += (uint32_t)__popc(s2) + ((uint32_t)__popc(s3) << 16);
        #pragma unroll
        for (int i = 0; i < 4; ++i) {
            uint32_t a = C[i][w];
            if (i == 0) MiP0 += (uint32_t)__popc(a & mk);
            if (i == 1) MiP0 += (uint32_t)__popc(a & mk) << 16;
            if (i == 2) MiP1 += (uint32_t)__popc(a & mk);
            if (i == 3) MiP1 += (uint32_t)__popc(a & mk) << 16;
            Mp[i*2+0] += (uint32_t)__popc(a & s0) + ((uint32_t)__popc(a & s1) << 16);
            Mp[i*2+1] += (uint32_t)__popc(a & s2) + ((uint32_t)__popc(a & s3) << 16);
        }
    }

    int Mi[4] = { (int)(MiP0 & 0xffffu), (int)(MiP0 >> 16),
                  (int)(MiP1 & 0xffffu), (int)(MiP1 >> 16) };
    int Mj[4] = { (int)(MjP0 & 0xffffu), (int)(MjP0 >> 16),
                  (int)(MjP1 & 0xffffu), (int)(MjP1 >> 16) };
    int M[16];
    #pragma unroll
    for (int i = 0; i < 4; ++i) {
        M[i*4+0] = (int)(Mp[i*2+0] & 0xffffu);
        M[i*4+1] = (int)(Mp[i*2+0] >> 16);
        M[i*4+2] = (int)(Mp[i*2+1] & 0xffffu);
        M[i*4+3] = (int)(Mp[i*2+1] >> 16);
    }

    // Cumulative table Mc[i][j] = N(a>=i, b>=j) -> cell counts via inclusion-exclusion
    int Mc[25];
    Mc[0] = TOT;
    Mc[1] = Mj[0]; Mc[2] = Mj[1]; Mc[3] = Mj[2]; Mc[4] = Mj[3];
    #pragma unroll
    for (int i = 1; i < 5; ++i) {
        Mc[i*5] = Mi[i-1];
        #pragma unroll
        for (int j = 1; j < 5; ++j) Mc[i*5+j] = M[(i-1)*4 + (j-1)];
    }
    int c[25];
    #pragma unroll
    for (int i = 0; i < 5; ++i)
        #pragma unroll
        for (int j = 0; j < 5; ++j) {
            int v = Mc[i*5+j];
            if (i < 4) v -= Mc[(i+1)*5+j];
            if (j < 4) v -= Mc[i*5+j+1];
            if (i < 4 && j < 4) v += Mc[(i+1)*5+j+1];
            c[i*5+j] = v;
        }

    const float invTot = 1.0f / (2.0f * (float)TOT);

    // symmetrized counts S = C + C^T (upper triangle incl. diag)
    int s00 = c[0]*2,  s11 = c[6]*2,  s22 = c[12]*2, s33 = c[18]*2, s44 = c[24]*2;
    int s01 = c[1]+c[5],   s02 = c[2]+c[10],  s03 = c[3]+c[15],  s04 = c[4]+c[20];
    int s12 = c[7]+c[11],  s13 = c[8]+c[16],  s14 = c[9]+c[21];
    int s23 = c[13]+c[17], s24 = c[14]+c[22];
    int s34 = c[19]+c[23];

    // contrast
    int ci = (s01 + s12 + s23 + s34) + 4*(s02 + s13 + s24) + 9*(s03 + s14) + 16*s04;
    feat[0] = 2.0f * invTot * (float)ci;

    // homogeneity
    float hoU = 0.5f*(float)(s01+s12+s23+s34)
              + 0.2f*(float)(s02+s13+s24)
              + 0.1f*(float)(s03+s14)
              + (1.0f/17.0f)*(float)s04;
    feat[1] = invTot * ((float)(s00+s11+s22+s33+s44) + 2.0f*hoU);

    // energy
    int e2i = s00*s00 + s11*s11 + s22*s22 + s33*s33 + s44*s44
            + 2*(s01*s01 + s02*s02 + s03*s03 + s04*s04
               + s12*s12 + s13*s13 + s14*s14
               + s23*s23 + s24*s24 + s34*s34);
    feat[2] = invTot * sqrtf((float)e2i);

    // correlation (symmetric => Pi == Pj)
    int t1 = s01+s11+s12+s13+s14;
    int t2 = s02+s12+s22+s23+s24;
    int t3 = s03+s13+s23+s33+s34;
    int t4 = s04+s14+s24+s34+s44;
    float mu  = invTot * (float)(t1 + 2*t2 + 3*t3 + 4*t4);
    float e2m = invTot * (float)(t1 + 4*t2 + 9*t3 + 16*t4);
    float varm = e2m - mu * mu;
    int wij = s11 + 4*s22 + 9*s33 + 16*s44
            + 2*(2*s12 + 3*s13 + 4*s14 + 6*s23 + 8*s24 + 12*s34);
    float cov = invTot * (float)wij - mu * mu;
    feat[3] = (varm < 1e-15f) ? 1.0f : __fdividef(cov, fmaxf(varm, 1e-30f));

    // entropy: off-diagonal cells counted twice
    float ent = 0.0f;
    {
        float g;
        g = (float)s00*invTot; ent += g*__log2f(g+1e-8f);
        g = (float)s11*invTot; ent += g*__log2f(g+1e-8f);
        g = (float)s22*invTot; ent += g*__log2f(g+1e-8f);
        g = (float)s33*invTot; ent += g*__log2f(g+1e-8f);
        g = (float)s44*invTot; ent += g*__log2f(g+1e-8f);
        g = (float)s01*invTot; ent += 2.0f*g*__log2f(g+1e-8f);
        g = (float)s02*invTot; ent += 2.0f*g*__log2f(g+1e-8f);
        g = (float)s03*invTot; ent += 2.0f*g*__log2f(g+1e-8f);
        g = (float)s04*invTot; ent += 2.0f*g*__log2f(g+1e-8f);
        g = (float)s12*invTot; ent += 2.0f*g*__log2f(g+1e-8f);
        g = (float)s13*invTot; ent += 2.0f*g*__log2f(g+1e-8f);
        g = (float)s14*invTot; ent += 2.0f*g*__log2f(g+1e-8f);
        g = (float)s23*invTot; ent += 2.0f*g*__log2f(g+1e-8f);
        g = (float)s24*invTot; ent += 2.0f*g*__log2f(g+1e-8f);
        g = (float)s34*invTot; ent += 2.0f*g*__log2f(g+1e-8f);
    }
    feat[4] = -ent;
}

static __device__ __forceinline__ void emit_feats(const float feat[5], int s1, int s2,
                                                  float valid, float* sacc, bool lane0)
{
    #pragma unroll
    for (int k = 0; k < 5; ++k) {
        float f = warp_sum(feat[k] * valid);
        if (lane0) {
            int base = 8 + 12 * k;
            atomicAdd(&sacc[base + s1], f);
            if (s2 >= 0) atomicAdd(&sacc[base + s2], f);
        }
    }
}

// 128 threads, min 6 blocks/SM => reg budget 85, 24 warps/SM resident,
// 968 blocks / (148*6) = 1.09 waves.
__global__ void __launch_bounds__(128, 6) glcm_feat_kernel(const float* __restrict__ x,
                                                           float* __restrict__ out)
{
    __shared__ float sacc[68];

    const int tid = threadIdx.x;
    const int b   = blockIdx.y;
    int wi = blockIdx.x * 128 + tid;
    const float valid = (wi < 15376) ? 1.0f : 0.0f;
    if (wi >= 15376) wi = 15375;
    const int ix = wi / 124;
    const int iy = wi - ix * 124;
    const bool lane0 = ((tid & 31) == 0);

    for (int i = tid; i < 68; i += 128) sacc[i] = 0.0f;
    __syncthreads();

    const float* base = x + ((size_t)b << 18) + (size_t)(ix * 4) * 512 + (size_t)(iy * 4);

    const float B1 = 0.5f;
    const float B2 = (float)(85.384 - 53.798);
    const float B3 = 85.384f;
    const float B4 = (float)(85.384 + 53.798);

    // cumulative bit-planes of the whole 17x17 window: C[l] = bitmap(q >= l+1)
    uint32_t C[4][11];
    #pragma unroll
    for (int j = 0; j < 4; ++j)
        #pragma unroll
        for (int w = 0; w < 11; ++w) C[j][w] = 0u;

    float sum = 0.f, sq = 0.f, mxv = 0.f, mnv = 1e30f;

    // ---- load, stats, quantize, build register bitmaps ----
    #pragma unroll
    for (int r = 0; r < 17; ++r) {
        const float* row = base + r * 512;
        const float4* p4 = (const float4*)row;   // window col start is 16B aligned
        float4 q0 = p4[0], q1 = p4[1], q2 = p4[2], q3 = p4[3];
        float px[17] = {q0.x,q0.y,q0.z,q0.w, q1.x,q1.y,q1.z,q1.w,
                        q2.x,q2.y,q2.z,q2.w, q3.x,q3.y,q3.z,q3.w, row[16]};
        uint32_t g1=0,g2=0,g3=0,g4=0;
        #pragma unroll
        for (int v = 0; v < 17; ++v) {
            float pv = px[v];
            sum += pv;
            float d = pv - G_MEAN_F;
            sq = fmaf(d, d, sq);
            mxv = fmaxf(mxv, pv);
            mnv = fminf(mnv, pv);
            uint32_t bit = 1u << v;
            if (pv >= B1) g1 |= bit;
            if (pv >= B2) g2 |= bit;
            if (pv >= B3) g3 |= bit;
            if (pv >= B4) g4 |= bit;
        }
        const int bp = r * 17;
        const int w0 = bp >> 5;
        const int sh = bp & 31;
        C[0][w0] |= g1 << sh;
        C[1][w0] |= g2 << sh;
        C[2][w0] |= g3 << sh;
        C[3][w0] |= g4 << sh;
        if (sh > 15) {   // row spills into next word (compile-time condition)
            C[0][w0+1] |= g1 >> (32 - sh);
            C[1][w0+1] |= g2 >> (32 - sh);
            C[2][w0+1] |= g3 >> (32 - sh);
            C[3][w0+1] |= g4 >> (32 - sh);
        }
    }

    // ---- stats + histogram channels (0..7) ----
    {
        int P1=0,P2=0,P3=0,P4=0;
        #pragma unroll
        for (int w = 0; w < 10; ++w) {
            P1 += __popc(C[0][w]); P2 += __popc(C[1][w]);
            P3 += __popc(C[2][w]); P4 += __popc(C[3][w]);
        }
        int h1 = P1 - P2, h2 = P2 - P3, h3 = P3 - P4, h4 = P4;

        const float inv289 = 1.0f / 289.0f;
        float mean  = sum * inv289;
        float var0  = fmaxf(sq * inv289 - (mean - G_MEAN_F) * (mean - G_MEAN_F), 0.0f);
        float stdv  = sqrtf(var0);
        float mnorm = mean * (1.0f / G_MEAN_F);

        float f;
        f = warp_sum(mnorm * valid);                            if (lane0) atomicAdd(&sacc[0], f);
        f = warp_sum((stdv * (1.0f/G_STD_F)) * valid);          if (lane0) atomicAdd(&sacc[1], f);
        f = warp_sum(((mxv - mnorm) * (1.0f/G_STD_F)) * valid); if (lane0) atomicAdd(&sacc[2], f);
        f = warp_sum(((mnorm - mnv) * (1.0f/G_STD_F)) * valid); if (lane0) atomicAdd(&sacc[3], f);

        int toti = h1 + h2 + h3 + h4;
        float invt = (toti > 0) ? __fdividef(1.0f, (float)toti) : 0.0f;
        f = warp_sum((float)h1 * invt * valid);                 if (lane0) atomicAdd(&sacc[4], f);
        f = warp_sum((float)h2 * invt * valid);                 if (lane0) atomicAdd(&sacc[5], f);
        f = warp_sum((float)h3 * invt * valid);                 if (lane0) atomicAdd(&sacc[6], f);
        f = warp_sum((float)h4 * invt * valid);                 if (lane0) atomicAdd(&sacc[7], f);
    }

    // ---- GLCM: 10 unique offsets (slots: (1,1)->1&5, (1,-1)->3&7) ----
    float feat[5];
    do_offset<0, 1>(C, feat); emit_feats(feat,  0, -1, valid, sacc, lane0);
    do_offset<1, 1>(C, feat); emit_feats(feat,  1,  5, valid, sacc, lane0);
    do_offset<1, 0>(C, feat); emit_feats(feat,  2, -1, valid, sacc, lane0);
    do_offset<1,-1>(C, feat); emit_feats(feat,  3,  7, valid, sacc, lane0);
    do_offset<0, 2>(C, feat); emit_feats(feat,  4, -1, valid, sacc, lane0);
    do_offset<2, 0>(C, feat); emit_feats(feat,  6, -1, valid, sacc, lane0);
    do_offset<0, 4>(C, feat); emit_feats(feat,  8, -1, valid, sacc, lane0);
    do_offset<3, 3>(C, feat); emit_feats(feat,  9, -1, valid, sacc, lane0);
    do_offset<4, 0>(C, feat); emit_feats(feat, 10, -1, valid, sacc, lane0);
    do_offset<3,-3>(C, feat); emit_feats(feat, 11, -1, valid, sacc, lane0);

    __syncthreads();
    if (tid < 68) atomicAdd(&out[b * 68 + tid], sacc[tid] * (1.0f / 15376.0f));
}

extern "C" void kernel_launch(void* const* d_in, const int* in_sizes, int n_in,
                              void* d_out, int out_size) {
    const float* x = (const float*)d_in[0];
    float* out = (float*)d_out;
    cudaMemsetAsync(out, 0, (size_t)out_size * sizeof(float), 0);
    dim3 grid(121, 8);   // 121*128 = 15488 >= 15376 windows per image, y = batch
    glcm_feat_kernel<<<grid, 128>>>(x, out);
}

// round 10
// speedup vs baseline: 2.8683x; 1.0731x over previous
#include <cuda_runtime.h>
#include <stdint.h>

#define G_MEAN_F 85.384f
#define G_STD_F  53.798f

static __device__ __forceinline__ float warp_sum(float f) {
    #pragma unroll
    for (int o = 16; o; o >>= 1) f += __shfl_down_sync(0xffffffffu, f, o);
    return f;
}

// Compile-time 289-bit validity mask for offset (DR,DC): bit p=r*17+c set iff
// (r,c) is a valid 'a' position: r <= 16-DR and (DC>=0 ? c <= 16-DC : c >= -DC)
template<int DR, int DC>
struct OffMask {
    uint32_t m[10];
    constexpr OffMask() : m{} {
        const int adc = DC < 0 ? -DC : DC;
        for (int r = 0; r <= 16 - DR; ++r)
            for (int c = 0; c < 17; ++c) {
                bool ok = (DC >= 0) ? (c <= 16 - DC) : (c >= adc);
                if (ok) { int p = r * 17 + c; m[p >> 5] |= (1u << (p & 31)); }
            }
    }
};

// GLCM features for one offset from 4 cumulative bit-planes (289-bit bitmaps).
// C[l] = bitmap of (q >= l+1). feat: {contrast, homogeneity, energy, corr, entropy}
// Accumulates only SYMMETRIC cumulative counts (14 scalars instead of 24):
//   X_pq = N(a>=p & b>=q) + N(a>=q & b>=p)   (p<q, 6)
//   D_p  = N(a>=p & b>=p)                    (4)
//   E_p  = N(a>=p) + N(b>=p)   over valid pairs (4)
// Symmetrized cells s_ij = U[i][j]-U[i+1][j]-U[i][j+1]+U[i+1][j+1] with
// U[0][0]=2*TOT, U[0][q]=E_q, U[p][p]=2*D_p, U[p][q]=X_pq.
template<int DR, int DC>
__device__ __forceinline__ void do_offset(const uint32_t C[4][11], float feat[5])
{
    constexpr int K   = DR * 17 + DC;
    constexpr int WO  = K >> 5;
    constexpr int SH  = K & 31;
    constexpr int ADC = DC < 0 ? -DC : DC;
    constexpr int NW  = ((17 - DR) * 17 + 31) >> 5;
    constexpr int TOT = (17 - DR) * (17 - ADC);
    constexpr OffMask<DR, DC> MK{};

    int X12=0, X13=0, X14=0, X23=0, X24=0, X34=0;
    int D1=0, D2=0, D3=0, D4=0;
    int E1=0, E2=0, E3=0, E4=0;

    #pragma unroll
    for (int w = 0; w < NW; ++w) {
        const uint32_t mk = MK.m[w];
        const uint32_t a0 = C[0][w], a1 = C[1][w], a2 = C[2][w], a3 = C[3][w];
        const uint32_t s0 = __funnelshift_r(C[0][w+WO], C[0][w+WO+1], SH) & mk;
        const uint32_t s1 = __funnelshift_r(C[1][w+WO], C[1][w+WO+1], SH) & mk;
        const uint32_t s2 = __funnelshift_r(C[2][w+WO], C[2][w+WO+1], SH) & mk;
        const uint32_t s3 = __funnelshift_r(C[3][w+WO], C[3][w+WO+1], SH) & mk;

        E1 += __popc(a0 & mk) + __popc(s0);
        E2 += __popc(a1 & mk) + __popc(s1);
        E3 += __popc(a2 & mk) + __popc(s2);
        E4 += __popc(a3 & mk) + __popc(s3);

        D1 += __popc(a0 & s0);
        D2 += __popc(a1 & s1);
        D3 += __popc(a2 & s2);
        D4 += __popc(a3 & s3);

        X12 += __popc(a0 & s1) + __popc(a1 & s0);
        X13 += __popc(a0 & s2) + __popc(a2 & s0);
        X14 += __popc(a0 & s3) + __popc(a3 & s0);
        X23 += __popc(a1 & s2) + __popc(a2 & s1);
        X24 += __popc(a1 & s3) + __popc(a3 & s1);
        X34 += __popc(a2 & s3) + __popc(a3 & s2);
    }

    // symmetrized cells directly from symmetric cumulative scalars
    const int U11 = 2*D1, U22 = 2*D2, U33 = 2*D3, U44 = 2*D4;
    const int s00 = 2*TOT - 2*E1 + U11;
    const int s01 = E1  - U11 - E2  + X12;
    const int s02 = E2  - X12 - E3  + X13;
    const int s03 = E3  - X13 - E4  + X14;
    const int s04 = E4  - X14;
    const int s11 = U11 - 2*X12 + U22;
    const int s12 = X12 - U22 - X13 + X23;
    const int s13 = X13 - X23 - X14 + X24;
    const int s14 = X14 - X24;
    const int s22 = U22 - 2*X23 + U33;
    const int s23 = X23 - U33 - X24 + X34;
    const int s24 = X24 - X34;
    const int s33 = U33 - 2*X34 + U44;
    const int s34 = X34 - U44;
    const int s44 = U44;

    const float invTot = 1.0f / (2.0f * (float)TOT);

    // contrast
    int ci = (s01 + s12 + s23 + s34) + 4*(s02 + s13 + s24) + 9*(s03 + s14) + 16*s04;
    feat[0] = 2.0f * invTot * (float)ci;

    // homogeneity
    float hoU = 0.5f*(float)(s01+s12+s23+s34)
              + 0.2f*(float)(s02+s13+s24)
              + 0.1f*(float)(s03+s14)
              + (1.0f/17.0f)*(float)s04;
    feat[1] = invTot * ((float)(s00+s11+s22+s33+s44) + 2.0f*hoU);

    // energy
    int e2i = s00*s00 + s11*s11 + s22*s22 + s33*s33 + s44*s44
            + 2*(s01*s01 + s02*s02 + s03*s03 + s04*s04
               + s12*s12 + s13*s13 + s14*s14
               + s23*s23 + s24*s24 + s34*s34);
    feat[2] = invTot * sqrtf((float)e2i);

    // correlation (symmetric => Pi == Pj)
    int t1 = s01+s11+s12+s13+s14;
    int t2 = s02+s12+s22+s23+s24;
    int t3 = s03+s13+s23+s33+s34;
    int t4 = s04+s14+s24+s34+s44;
    float mu  = invTot * (float)(t1 + 2*t2 + 3*t3 + 4*t4);
    float e2m = invTot * (float)(t1 + 4*t2 + 9*t3 + 16*t4);
    float varm = e2m - mu * mu;
    int wij = s11 + 4*s22 + 9*s33 + 16*s44
            + 2*(2*s12 + 3*s13 + 4*s14 + 6*s23 + 8*s24 + 12*s34);
    float cov = invTot * (float)wij - mu * mu;
    feat[3] = (varm < 1e-15f) ? 1.0f : __fdividef(cov, fmaxf(varm, 1e-30f));

    // entropy: off-diagonal cells counted twice
    float ent = 0.0f;
    {
        float g;
        g = (float)s00*invTot; ent += g*__log2f(g+1e-8f);
        g = (float)s11*invTot; ent += g*__log2f(g+1e-8f);
        g = (float)s22*invTot; ent += g*__log2f(g+1e-8f);
        g = (float)s33*invTot; ent += g*__log2f(g+1e-8f);
        g = (float)s44*invTot; ent += g*__log2f(g+1e-8f);
        g = (float)s01*invTot; ent += 2.0f*g*__log2f(g+1e-8f);
        g = (float)s02*invTot; ent += 2.0f*g*__log2f(g+1e-8f);
        g = (float)s03*invTot; ent += 2.0f*g*__log2f(g+1e-8f);
        g = (float)s04*invTot; ent += 2.0f*g*__log2f(g+1e-8f);
        g = (float)s12*invTot; ent += 2.0f*g*__log2f(g+1e-8f);
        g = (float)s13*invTot; ent += 2.0f*g*__log2f(g+1e-8f);
        g = (float)s14*invTot; ent += 2.0f*g*__log2f(g+1e-8f);
        g = (float)s23*invTot; ent += 2.0f*g*__log2f(g+1e-8f);
        g = (float)s24*invTot; ent += 2.0f*g*__log2f(g+1e-8f);
        g = (float)s34*invTot; ent += 2.0f*g*__log2f(g+1e-8f);
    }
    feat[4] = -ent;
}

static __device__ __forceinline__ void emit_feats(const float feat[5], int s1, int s2,
                                                  float valid, float* sacc, bool lane0)
{
    #pragma unroll
    for (int k = 0; k < 5; ++k) {
        float f = warp_sum(feat[k] * valid);
        if (lane0) {
            int base = 8 + 12 * k;
            atomicAdd(&sacc[base + s1], f);
            if (s2 >= 0) atomicAdd(&sacc[base + s2], f);
        }
    }
}

// 128 threads, min 6 blocks/SM => reg budget 85, 24 warps/SM resident.
// True live set ~70 after symmetric-accumulator rewrite => expect no spills.
__global__ void __launch_bounds__(128, 6) glcm_feat_kernel(const float* __restrict__ x,
                                                           float* __restrict__ out)
{
    __shared__ float sacc[68];

    const int tid = threadIdx.x;
    const int b   = blockIdx.y;
    int wi = blockIdx.x * 128 + tid;
    const float valid = (wi < 15376) ? 1.0f : 0.0f;
    if (wi >= 15376) wi = 15375;
    const int ix = wi / 124;
    const int iy = wi - ix * 124;
    const bool lane0 = ((tid & 31) == 0);

    for (int i = tid; i < 68; i += 128) sacc[i] = 0.0f;
    __syncthreads();

    const float* base = x + ((size_t)b << 18) + (size_t)(ix * 4) * 512 + (size_t)(iy * 4);

    const float B1 = 0.5f;
    const float B2 = (float)(85.384 - 53.798);
    const float B3 = 85.384f;
    const float B4 = (float)(85.384 + 53.798);

    // cumulative bit-planes of the whole 17x17 window: C[l] = bitmap(q >= l+1)
    uint32_t C[4][11];
    #pragma unroll
    for (int j = 0; j < 4; ++j)
        #pragma unroll
        for (int w = 0; w < 11; ++w) C[j][w] = 0u;

    float sum = 0.f, sq = 0.f, mxv = 0.f, mnv = 1e30f;

    // ---- load, stats, quantize, build register bitmaps ----
    #pragma unroll
    for (int r = 0; r < 17; ++r) {
        const float* row = base + r * 512;
        const float4* p4 = (const float4*)row;   // window col start is 16B aligned
        float4 q0 = p4[0], q1 = p4[1], q2 = p4[2], q3 = p4[3];
        float px[17] = {q0.x,q0.y,q0.z,q0.w, q1.x,q1.y,q1.z,q1.w,
                        q2.x,q2.y,q2.z,q2.w, q3.x,q3.y,q3.z,q3.w, row[16]};
        uint32_t g1=0,g2=0,g3=0,g4=0;
        #pragma unroll
        for (int v = 0; v < 17; ++v) {
            float pv = px[v];
            sum += pv;
            float d = pv - G_MEAN_F;
            sq = fmaf(d, d, sq);
            mxv = fmaxf(mxv, pv);
            mnv = fminf(mnv, pv);
            uint32_t bit = 1u << v;
            if (pv >= B1) g1 |= bit;
            if (pv >= B2) g2 |= bit;
            if (pv >= B3) g3 |= bit;
            if (pv >= B4) g4 |= bit;
        }
        const int bp = r * 17;
        const int w0 = bp >> 5;
        const int sh = bp & 31;
        C[0][w0] |= g1 << sh;
        C[1][w0] |= g2 << sh;
        C[2][w0] |= g3 << sh;
        C[3][w0] |= g4 << sh;
        if (sh > 15) {   // row spills into next word (compile-time condition)
            C[0][w0+1] |= g1 >> (32 - sh);
            C[1][w0+1] |= g2 >> (32 - sh);
            C[2][w0+1] |= g3 >> (32 - sh);
            C[3][w0+1] |= g4 >> (32 - sh);
        }
    }

    // ---- stats + histogram channels (0..7) ----
    {
        int P1=0,P2=0,P3=0,P4=0;
        #pragma unroll
        for (int w = 0; w < 10; ++w) {
            P1 += __popc(C[0][w]); P2 += __popc(C[1][w]);
            P3 += __popc(C[2][w]); P4 += __popc(C[3][w]);
        }
        int h1 = P1 - P2, h2 = P2 - P3, h3 = P3 - P4, h4 = P4;

        const float inv289 = 1.0f / 289.0f;
        float mean  = sum * inv289;
        float var0  = fmaxf(sq * inv289 - (mean - G_MEAN_F) * (mean - G_MEAN_F), 0.0f);
        float stdv  = sqrtf(var0);
        float mnorm = mean * (1.0f / G_MEAN_F);

        float f;
        f = warp_sum(mnorm * valid);                            if (lane0) atomicAdd(&sacc[0], f);
        f = warp_sum((stdv * (1.0f/G_STD_F)) * valid);          if (lane0) atomicAdd(&sacc[1], f);
        f = warp_sum(((mxv - mnorm) * (1.0f/G_STD_F)) * valid); if (lane0) atomicAdd(&sacc[2], f);
        f = warp_sum(((mnorm - mnv) * (1.0f/G_STD_F)) * valid); if (lane0) atomicAdd(&sacc[3], f);

        int toti = h1 + h2 + h3 + h4;
        float invt = (toti > 0) ? __fdividef(1.0f, (float)toti) : 0.0f;
        f = warp_sum((float)h1 * invt * valid);                 if (lane0) atomicAdd(&sacc[4], f);
        f = warp_sum((float)h2 * invt * valid);                 if (lane0) atomicAdd(&sacc[5], f);
        f = warp_sum((float)h3 * invt * valid);                 if (lane0) atomicAdd(&sacc[6], f);
        f = warp_sum((float)h4 * invt * valid);                 if (lane0) atomicAdd(&sacc[7], f);
    }

    // ---- GLCM: 10 unique offsets (slots: (1,1)->1&5, (1,-1)->3&7) ----
    float feat[5];
    do_offset<0, 1>(C, feat); emit_feats(feat,  0, -1, valid, sacc, lane0);
    do_offset<1, 1>(C, feat); emit_feats(feat,  1,  5, valid, sacc, lane0);
    do_offset<1, 0>(C, feat); emit_feats(feat,  2, -1, valid, sacc, lane0);
    do_offset<1,-1>(C, feat); emit_feats(feat,  3,  7, valid, sacc, lane0);
    do_offset<0, 2>(C, feat); emit_feats(feat,  4, -1, valid, sacc, lane0);
    do_offset<2, 0>(C, feat); emit_feats(feat,  6, -1, valid, sacc, lane0);
    do_offset<0, 4>(C, feat); emit_feats(feat,  8, -1, valid, sacc, lane0);
    do_offset<3, 3>(C, feat); emit_feats(feat,  9, -1, valid, sacc, lane0);
    do_offset<4, 0>(C, feat); emit_feats(feat, 10, -1, valid, sacc, lane0);
    do_offset<3,-3>(C, feat); emit_feats(feat, 11, -1, valid, sacc, lane0);

    __syncthreads();
    if (tid < 68) atomicAdd(&out[b * 68 + tid], sacc[tid] * (1.0f / 15376.0f));
}

extern "C" void kernel_launch(void* const* d_in, const int* in_sizes, int n_in,
                              void* d_out, int out_size) {
    const float* x = (const float*)d_in[0];
    float* out = (float*)d_out;
    cudaMemsetAsync(out, 0, (size_t)out_size * sizeof(float), 0);
    dim3 grid(121, 8);   // 121*128 = 15488 >= 15376 windows per image, y = batch
    glcm_feat_kernel<<<grid, 128>>>(x, out);
}

// round 11
// speedup vs baseline: 3.1002x; 1.0808x over previous
#include <cuda_runtime.h>
#include <stdint.h>

#define G_MEAN_F 85.384f
#define G_STD_F  53.798f

static __device__ __forceinline__ float warp_sum(float f) {
    #pragma unroll
    for (int o = 16; o; o >>= 1) f += __shfl_down_sync(0xffffffffu, f, o);
    return f;
}

// Compile-time 289-bit validity mask for offset (DR,DC): bit p=r*17+c set iff
// (r,c) is a valid 'a' position: r <= 16-DR and (DC>=0 ? c <= 16-DC : c >= -DC)
template<int DR, int DC>
struct OffMask {
    uint32_t m[10];
    constexpr OffMask() : m{} {
        const int adc = DC < 0 ? -DC : DC;
        for (int r = 0; r <= 16 - DR; ++r)
            for (int c = 0; c < 17; ++c) {
                bool ok = (DC >= 0) ? (c <= 16 - DC) : (c >= adc);
                if (ok) { int p = r * 17 + c; m[p >> 5] |= (1u << (p & 31)); }
            }
    }
};

// GLCM features for one offset from 4 cumulative bit-planes (289-bit bitmaps).
// C[l] = bitmap of (q >= l+1). feat: {contrast, homogeneity, energy, corr, entropy}
// Accumulates only SYMMETRIC cumulative counts (14 scalars instead of 24):
//   X_pq = N(a>=p & b>=q) + N(a>=q & b>=p)   (p<q, 6)
//   D_p  = N(a>=p & b>=p)                    (4)
//   E_p  = N(a>=p) + N(b>=p)   over valid pairs (4)
template<int DR, int DC>
__device__ __forceinline__ void do_offset(const uint32_t C[4][11], float feat[5])
{
    constexpr int K   = DR * 17 + DC;
    constexpr int WO  = K >> 5;
    constexpr int SH  = K & 31;
    constexpr int ADC = DC < 0 ? -DC : DC;
    constexpr int NW  = ((17 - DR) * 17 + 31) >> 5;
    constexpr int TOT = (17 - DR) * (17 - ADC);
    constexpr OffMask<DR, DC> MK{};

    int X12=0, X13=0, X14=0, X23=0, X24=0, X34=0;
    int D1=0, D2=0, D3=0, D4=0;
    int E1=0, E2=0, E3=0, E4=0;

    #pragma unroll
    for (int w = 0; w < NW; ++w) {
        const uint32_t mk = MK.m[w];
        const uint32_t a0 = C[0][w], a1 = C[1][w], a2 = C[2][w], a3 = C[3][w];
        const uint32_t s0 = __funnelshift_r(C[0][w+WO], C[0][w+WO+1], SH) & mk;
        const uint32_t s1 = __funnelshift_r(C[1][w+WO], C[1][w+WO+1], SH) & mk;
        const uint32_t s2 = __funnelshift_r(C[2][w+WO], C[2][w+WO+1], SH) & mk;
        const uint32_t s3 = __funnelshift_r(C[3][w+WO], C[3][w+WO+1], SH) & mk;

        E1 += __popc(a0 & mk) + __popc(s0);
        E2 += __popc(a1 & mk) + __popc(s1);
        E3 += __popc(a2 & mk) + __popc(s2);
        E4 += __popc(a3 & mk) + __popc(s3);

        D1 += __popc(a0 & s0);
        D2 += __popc(a1 & s1);
        D3 += __popc(a2 & s2);
        D4 += __popc(a3 & s3);

        X12 += __popc(a0 & s1) + __popc(a1 & s0);
        X13 += __popc(a0 & s2) + __popc(a2 & s0);
        X14 += __popc(a0 & s3) + __popc(a3 & s0);
        X23 += __popc(a1 & s2) + __popc(a2 & s1);
        X24 += __popc(a1 & s3) + __popc(a3 & s1);
        X34 += __popc(a2 & s3) + __popc(a3 & s2);
    }

    // symmetrized cells directly from symmetric cumulative scalars
    const int U11 = 2*D1, U22 = 2*D2, U33 = 2*D3, U44 = 2*D4;
    const int s00 = 2*TOT - 2*E1 + U11;
    const int s01 = E1  - U11 - E2  + X12;
    const int s02 = E2  - X12 - E3  + X13;
    const int s03 = E3  - X13 - E4  + X14;
    const int s04 = E4  - X14;
    const int s11 = U11 - 2*X12 + U22;
    const int s12 = X12 - U22 - X13 + X23;
    const int s13 = X13 - X23 - X14 + X24;
    const int s14 = X14 - X24;
    const int s22 = U22 - 2*X23 + U33;
    const int s23 = X23 - U33 - X24 + X34;
    const int s24 = X24 - X34;
    const int s33 = U33 - 2*X34 + U44;
    const int s34 = X34 - U44;
    const int s44 = U44;

    const float invTot = 1.0f / (2.0f * (float)TOT);

    // contrast
    int ci = (s01 + s12 + s23 + s34) + 4*(s02 + s13 + s24) + 9*(s03 + s14) + 16*s04;
    feat[0] = 2.0f * invTot * (float)ci;

    // homogeneity
    float hoU = 0.5f*(float)(s01+s12+s23+s34)
              + 0.2f*(float)(s02+s13+s24)
              + 0.1f*(float)(s03+s14)
              + (1.0f/17.0f)*(float)s04;
    feat[1] = invTot * ((float)(s00+s11+s22+s33+s44) + 2.0f*hoU);

    // energy
    int e2i = s00*s00 + s11*s11 + s22*s22 + s33*s33 + s44*s44
            + 2*(s01*s01 + s02*s02 + s03*s03 + s04*s04
               + s12*s12 + s13*s13 + s14*s14
               + s23*s23 + s24*s24 + s34*s34);
    feat[2] = invTot * sqrtf((float)e2i);

    // correlation (symmetric => Pi == Pj)
    int t1 = s01+s11+s12+s13+s14;
    int t2 = s02+s12+s22+s23+s24;
    int t3 = s03+s13+s23+s33+s34;
    int t4 = s04+s14+s24+s34+s44;
    float mu  = invTot * (float)(t1 + 2*t2 + 3*t3 + 4*t4);
    float e2m = invTot * (float)(t1 + 4*t2 + 9*t3 + 16*t4);
    float varm = e2m - mu * mu;
    int wij = s11 + 4*s22 + 9*s33 + 16*s44
            + 2*(2*s12 + 3*s13 + 4*s14 + 6*s23 + 8*s24 + 12*s34);
    float cov = invTot * (float)wij - mu * mu;
    feat[3] = (varm < 1e-15f) ? 1.0f : __fdividef(cov, fmaxf(varm, 1e-30f));

    // entropy: off-diagonal cells counted twice
    float ent = 0.0f;
    {
        float g;
        g = (float)s00*invTot; ent += g*__log2f(g+1e-8f);
        g = (float)s11*invTot; ent += g*__log2f(g+1e-8f);
        g = (float)s22*invTot; ent += g*__log2f(g+1e-8f);
        g = (float)s33*invTot; ent += g*__log2f(g+1e-8f);
        g = (float)s44*invTot; ent += g*__log2f(g+1e-8f);
        g = (float)s01*invTot; ent += 2.0f*g*__log2f(g+1e-8f);
        g = (float)s02*invTot; ent += 2.0f*g*__log2f(g+1e-8f);
        g = (float)s03*invTot; ent += 2.0f*g*__log2f(g+1e-8f);
        g = (float)s04*invTot; ent += 2.0f*g*__log2f(g+1e-8f);
        g = (float)s12*invTot; ent += 2.0f*g*__log2f(g+1e-8f);
        g = (float)s13*invTot; ent += 2.0f*g*__log2f(g+1e-8f);
        g = (float)s14*invTot; ent += 2.0f*g*__log2f(g+1e-8f);
        g = (float)s23*invTot; ent += 2.0f*g*__log2f(g+1e-8f);
        g = (float)s24*invTot; ent += 2.0f*g*__log2f(g+1e-8f);
        g = (float)s34*invTot; ent += 2.0f*g*__log2f(g+1e-8f);
    }
    feat[4] = -ent;
}

static __device__ __forceinline__ void emit_feats(const float feat[5], int s1, int s2,
                                                  float valid, float* sacc, bool lane0)
{
    #pragma unroll
    for (int k = 0; k < 5; ++k) {
        float f = warp_sum(feat[k] * valid);
        if (lane0) {
            int base = 8 + 12 * k;
            atomicAdd(&sacc[base + s1], f);
            if (s2 >= 0) atomicAdd(&sacc[base + s2], f);
        }
    }
}

// 128 threads, min 5 blocks/SM => reg budget 102 (proven spill-free regime),
// with the lighter symmetric-accumulator algorithm.
__global__ void __launch_bounds__(128, 5) glcm_feat_kernel(const float* __restrict__ x,
                                                           float* __restrict__ out)
{
    __shared__ float sacc[68];

    const int tid = threadIdx.x;
    const int b   = blockIdx.y;
    int wi = blockIdx.x * 128 + tid;
    const float valid = (wi < 15376) ? 1.0f : 0.0f;
    if (wi >= 15376) wi = 15375;
    const int ix = wi / 124;
    const int iy = wi - ix * 124;
    const bool lane0 = ((tid & 31) == 0);

    for (int i = tid; i < 68; i += 128) sacc[i] = 0.0f;
    __syncthreads();

    const float* base = x + ((size_t)b << 18) + (size_t)(ix * 4) * 512 + (size_t)(iy * 4);

    const float B1 = 0.5f;
    const float B2 = (float)(85.384 - 53.798);
    const float B3 = 85.384f;
    const float B4 = (float)(85.384 + 53.798);

    // cumulative bit-planes of the whole 17x17 window: C[l] = bitmap(q >= l+1)
    uint32_t C[4][11];
    #pragma unroll
    for (int j = 0; j < 4; ++j)
        #pragma unroll
        for (int w = 0; w < 11; ++w) C[j][w] = 0u;

    float sum = 0.f, sq = 0.f, mxv = 0.f, mnv = 1e30f;

    // ---- load, stats, quantize, build register bitmaps ----
    #pragma unroll
    for (int r = 0; r < 17; ++r) {
        const float* row = base + r * 512;
        const float4* p4 = (const float4*)row;   // window col start is 16B aligned
        float4 q0 = p4[0], q1 = p4[1], q2 = p4[2], q3 = p4[3];
        float px[17] = {q0.x,q0.y,q0.z,q0.w, q1.x,q1.y,q1.z,q1.w,
                        q2.x,q2.y,q2.z,q2.w, q3.x,q3.y,q3.z,q3.w, row[16]};
        uint32_t g1=0,g2=0,g3=0,g4=0;
        #pragma unroll
        for (int v = 0; v < 17; ++v) {
            float pv = px[v];
            sum += pv;
            float d = pv - G_MEAN_F;
            sq = fmaf(d, d, sq);
            mxv = fmaxf(mxv, pv);
            mnv = fminf(mnv, pv);
            uint32_t bit = 1u << v;
            if (pv >= B1) g1 |= bit;
            if (pv >= B2) g2 |= bit;
            if (pv >= B3) g3 |= bit;
            if (pv >= B4) g4 |= bit;
        }
        const int bp = r * 17;
        const int w0 = bp >> 5;
        const int sh = bp & 31;
        C[0][w0] |= g1 << sh;
        C[1][w0] |= g2 << sh;
        C[2][w0] |= g3 << sh;
        C[3][w0] |= g4 << sh;
        if (sh > 15) {   // row spills into next word (compile-time condition)
            C[0][w0+1] |= g1 >> (32 - sh);
            C[1][w0+1] |= g2 >> (32 - sh);
            C[2][w0+1] |= g3 >> (32 - sh);
            C[3][w0+1] |= g4 >> (32 - sh);
        }
    }

    // ---- stats + histogram channels (0..7) ----
    {
        int P1=0,P2=0,P3=0,P4=0;
        #pragma unroll
        for (int w = 0; w < 10; ++w) {
            P1 += __popc(C[0][w]); P2 += __popc(C[1][w]);
            P3 += __popc(C[2][w]); P4 += __popc(C[3][w]);
        }
        int h1 = P1 - P2, h2 = P2 - P3, h3 = P3 - P4, h4 = P4;

        const float inv289 = 1.0f / 289.0f;
        float mean  = sum * inv289;
        float var0  = fmaxf(sq * inv289 - (mean - G_MEAN_F) * (mean - G_MEAN_F), 0.0f);
        float stdv  = sqrtf(var0);
        float mnorm = mean * (1.0f / G_MEAN_F);

        float f;
        f = warp_sum(mnorm * valid);                            if (lane0) atomicAdd(&sacc[0], f);
        f = warp_sum((stdv * (1.0f/G_STD_F)) * valid);          if (lane0) atomicAdd(&sacc[1], f);
        f = warp_sum(((mxv - mnorm) * (1.0f/G_STD_F)) * valid); if (lane0) atomicAdd(&sacc[2], f);
        f = warp_sum(((mnorm - mnv) * (1.0f/G_STD_F)) * valid); if (lane0) atomicAdd(&sacc[3], f);

        int toti = h1 + h2 + h3 + h4;
        float invt = (toti > 0) ? __fdividef(1.0f, (float)toti) : 0.0f;
        f = warp_sum((float)h1 * invt * valid);                 if (lane0) atomicAdd(&sacc[4], f);
        f = warp_sum((float)h2 * invt * valid);                 if (lane0) atomicAdd(&sacc[5], f);
        f = warp_sum((float)h3 * invt * valid);                 if (lane0) atomicAdd(&sacc[6], f);
        f = warp_sum((float)h4 * invt * valid);                 if (lane0) atomicAdd(&sacc[7], f);
    }

    // ---- GLCM: 10 unique offsets (slots: (1,1)->1&5, (1,-1)->3&7) ----
    float feat[5];
    do_offset<0, 1>(C, feat); emit_feats(feat,  0, -1, valid, sacc, lane0);
    do_offset<1, 1>(C, feat); emit_feats(feat,  1,  5, valid, sacc, lane0);
    do_offset<1, 0>(C, feat); emit_feats(feat,  2, -1, valid, sacc, lane0);
    do_offset<1,-1>(C, feat); emit_feats(feat,  3,  7, valid, sacc, lane0);
    do_offset<0, 2>(C, feat); emit_feats(feat,  4, -1, valid, sacc, lane0);
    do_offset<2, 0>(C, feat); emit_feats(feat,  6, -1, valid, sacc, lane0);
    do_offset<0, 4>(C, feat); emit_feats(feat,  8, -1, valid, sacc, lane0);
    do_offset<3, 3>(C, feat); emit_feats(feat,  9, -1, valid, sacc, lane0);
    do_offset<4, 0>(C, feat); emit_feats(feat, 10, -1, valid, sacc, lane0);
    do_offset<3,-3>(C, feat); emit_feats(feat, 11, -1, valid, sacc, lane0);

    __syncthreads();
    if (tid < 68) atomicAdd(&out[b * 68 + tid], sacc[tid] * (1.0f / 15376.0f));
}

extern "C" void kernel_launch(void* const* d_in, const int* in_sizes, int n_in,
                              void* d_out, int out_size) {
    const float* x = (const float*)d_in[0];
    float* out = (float*)d_out;
    cudaMemsetAsync(out, 0, (size_t)out_size * sizeof(float), 0);
    dim3 grid(121, 8);   // 121*128 = 15488 >= 15376 windows per image, y = batch
    glcm_feat_kernel<<<grid, 128>>>(x, out);
}